// round 14
// baseline (speedup 1.0000x reference)
#include <cuda_runtime.h>
#include <stdint.h>

// Problem constants (fixed by the reference):
//   B=32, T=512, D=384, DUR_MAX=8, L = T*(DUR_MAX-1) = 3584
#define BB 32
#define TT 512
#define DD 384
#define LL 3584
#define D8 (DD / 8)               // 48 float8 per frame
#define MAIN_ELEMS (BB * LL * DD) // 44040192 fp32 elements of expanded output
#define BPR (LL / 32)             // 112 blocks per batch row (32 frames per block)
#define NBLK (BB * BPR)           // 3584 blocks
#define NTHR 256

// 256-bit global load (non-coherent) — sm_100+ PTX v8.f32
__device__ __forceinline__ void ldg_nc_v8(const float* p, float* r) {
    asm volatile("ld.global.nc.v8.f32 {%0,%1,%2,%3,%4,%5,%6,%7}, [%8];"
                 : "=f"(r[0]), "=f"(r[1]), "=f"(r[2]), "=f"(r[3]),
                   "=f"(r[4]), "=f"(r[5]), "=f"(r[6]), "=f"(r[7])
                 : "l"(p));
}
// 256-bit streaming (evict-first) global store
__device__ __forceinline__ void stcs_v8(float* p, const float* r) {
    asm volatile("st.global.cs.v8.f32 [%0], {%1,%2,%3,%4,%5,%6,%7,%8};"
                 :: "l"(p),
                    "f"(r[0]), "f"(r[1]), "f"(r[2]), "f"(r[3]),
                    "f"(r[4]), "f"(r[5]), "f"(r[6]), "f"(r[7])
                 : "memory");
}

// ---------------------------------------------------------------------------
// R14 experiment: identical scan/search to the verified 31.2us kernel; the
// gather/store path uses 256-bit STG.CS / LDG.NC (v8.f32) instead of 128-bit.
// A frame = 48 float8, so 2 frames = exactly 3 warp-wide v8 accesses with a
// per-lane frame select. Warp owns 4 frames = 2 pairs = 6 v8 loads + 6 v8
// stores, all independent. Tests whether halving LTS write-request count per
// byte moves the write-path floor (store-path sweep so far:
// stcs128=31.2 < wt=37.3 < wb=37.6 < tma=39.0).
// ---------------------------------------------------------------------------
__global__ void __launch_bounds__(NTHR) lenreg_v8_kernel(
        const float*  __restrict__ xf,
        const int*    __restrict__ dur_words,
        float*        __restrict__ outf,
        int mode, float* __restrict__ tail_f, long long* __restrict__ tail_i) {
    int b        = blockIdx.x / BPR;
    int blkInRow = blockIdx.x % BPR;
    int tid  = threadIdx.x;
    int lane = tid & 31;
    int warp = tid >> 5;

    __shared__ int s_is64;
    __shared__ int cum[TT];
    __shared__ int s_wsum[8];
    __shared__ int s_woff[8];

    // --- dtype detection (max word index 2111: in-bounds for both layouts;
    //     int64-LE values <8 have all odd words zero; int32 random durations
    //     all-zero w.p. 8^-32) ---
    if (warp == 0) {
        int w = dur_words[(b * 32 + lane) * 2 + 1];
        unsigned any = __ballot_sync(0xFFFFFFFFu, w != 0);
        if (lane == 0) s_is64 = (any == 0u) ? 1 : 0;
    }
    __syncthreads();
    int is64 = s_is64;

    // --- load 2 durations per thread, pair-wise inclusive scan ---
    int t0 = tid * 2, t1 = tid * 2 + 1;
    long base = (long)b * TT;
    int d0 = dur_words[is64 ? (base + t0) * 2 : (base + t0)];
    int d1 = dur_words[is64 ? (base + t1) * 2 : (base + t1)];
    int e0 = d0 < 1 ? 1 : d0;
    int e1 = d1 < 1 ? 1 : d1;

    int v = e0 + e1;
#pragma unroll
    for (int off = 1; off < 32; off <<= 1) {
        int u = __shfl_up_sync(0xFFFFFFFFu, v, off);
        if (lane >= off) v += u;
    }
    if (lane == 31) s_wsum[warp] = v;
    __syncthreads();
    if (warp == 0 && lane < 8) {
        int s = s_wsum[lane];
#pragma unroll
        for (int off = 1; off < 8; off <<= 1) {
            int u = __shfl_up_sync(0xFFu, s, off);
            if (lane >= off) s += u;
        }
        s_woff[lane] = s;
    }
    __syncthreads();
    int inc = v + (warp > 0 ? s_woff[warp - 1] : 0);
    cum[t1] = inc;
    cum[t0] = inc - e1;
    __syncthreads();
    int mel = s_woff[7];

    // --- binary search: lanes 0..3 search the warp's 4 frames ---
    int fbase = blkInRow * 32 + warp * 4;
    int f = fbase + (lane & 3);
    int pos = 0;
#pragma unroll
    for (int step = 256; step >= 1; step >>= 1) {
        if (pos + step <= TT && cum[pos + step - 1] <= f) pos += step;
    }
    if (pos > TT - 1) pos = TT - 1;
    // source base in float8 units, or -1 if masked
    int src = (f < mel) ? (int)((b * TT + pos) * D8) : -1;

    int s0 = __shfl_sync(0xFFFFFFFFu, src, 0);
    int s1 = __shfl_sync(0xFFFFFFFFu, src, 1);
    int s2 = __shfl_sync(0xFFFFFFFFu, src, 2);
    int s3 = __shfl_sync(0xFFFFFFFFu, src, 3);

    // --- gather+store: 2 frame-pairs, 3 v8 accesses each ---
    long obase8 = ((long)b * LL + fbase) * D8;   // output base in float8 units
#pragma unroll
    for (int p = 0; p < 2; p++) {
        int sA = (p == 0) ? s0 : s2;
        int sB = (p == 0) ? s1 : s3;
        float r[3][8];
#pragma unroll
        for (int k = 0; k < 3; k++) {
            int e  = k * 32 + lane;          // 0..95 within the 2-frame pair
            int hi = (e >= D8) ? 1 : 0;      // second frame of the pair?
            int off = e - (hi ? D8 : 0);
            int s  = hi ? sB : sA;
            if (s < 0) {
#pragma unroll
                for (int q = 0; q < 8; q++) r[k][q] = 0.f;
            } else {
                ldg_nc_v8(xf + ((long)s + off) * 8, r[k]);
            }
        }
        long pb8 = obase8 + (long)p * 2 * D8;
#pragma unroll
        for (int k = 0; k < 3; k++) {
            stcs_v8(outf + (pb8 + k * 32 + lane) * 8, r[k]);
        }
    }

    // --- mel_len tail (one writer per batch row) ---
    if (blkInRow == 0 && tid == 0) {
        if (mode == 1)      tail_f[b] = (float)mel;
        else if (mode == 2) tail_i[b] = (long long)mel;
    }
}

// ---------------------------------------------------------------------------
extern "C" void kernel_launch(void* const* d_in, const int* in_sizes, int n_in,
                              void* d_out, int out_size) {
    const float* x   = (const float*)d_in[0];
    const int*   dur = (const int*)d_in[1];
    (void)in_sizes; (void)n_in;

    int extra = out_size - MAIN_ELEMS;
    int mode = 0;
    if (extra >= 2 * BB)  mode = 2;   // tail as int64
    else if (extra >= BB) mode = 1;   // tail as fp32

    float*     tail_f = (float*)d_out + MAIN_ELEMS;
    long long* tail_i = (long long*)((char*)d_out + (size_t)MAIN_ELEMS * 4);

    lenreg_v8_kernel<<<NBLK, NTHR>>>(x, dur, (float*)d_out,
                                     mode, tail_f, tail_i);
}

// round 15
// speedup vs baseline: 1.1992x; 1.1992x over previous
#include <cuda_runtime.h>
#include <stdint.h>

// Problem constants (fixed by the reference):
//   B=32, T=512, D=384, DUR_MAX=8, L = T*(DUR_MAX-1) = 3584
#define BB 32
#define TT 512
#define DD 384
#define LL 3584
#define D4 (DD / 4)               // 96 float4 per row = 3 warp-wide accesses
#define MAIN_ELEMS (BB * LL * DD) // 44040192 fp32 elements of expanded output
#define BPR (LL / 32)             // 112 blocks per batch row (32 frames per block)
#define NBLK (BB * BPR)           // 3584 blocks
#define NTHR 256

// ---------------------------------------------------------------------------
// FINAL fused length-regulator kernel — verified best across 14 rounds.
// Measured 31.20us (x5, one 32.48 outlier) = 176MB mandatory output writes +
// ~25MB x reads at ~6.4TB/s effective: the sm_103a write-dominated HBM floor
// (x stays L2-resident in steady state).
// Measured design decisions:
//   * fused single launch (split scan+gather: +2us)
//   * 128-bit __stcs streaming stores — complete store-path sweep:
//       stcs128=31.2 < wt=37.3 ~ v8stcs=37.4 < wb=37.6 < TMA-staged=39.0 us
//     (evict-first 128-bit stores give single-wavefront full-line write
//      bursts; 256-bit splits into replays; wb/wt churn L2 sector state;
//      smem-staged TMA pays an extra smem pass + occupancy loss)
//   * 3584 blocks x 256 thr, warp-per-4-frames (multi-wave CTA parallelism
//     needed: 448-block single-wave variant regressed to 33.3us)
//   * 3 warp-wide float4 accesses per frame: perfectly coalesced, zero
//     div/mod in the hot path; 12 independent __ldg gathers per lane
// Per block: dtype-detect (int64 vs int32 duration layout via ballot on odd
// words), 512-token inclusive scan of max(dur,1) (pair-scan, 2 elems/thread),
// lanes 0..3 binary-search the warp's 4 frames (searchsorted right), gather,
// streaming store. mel_len written to output tail (dtype-adaptive).
// ---------------------------------------------------------------------------
__global__ void __launch_bounds__(NTHR) lenreg_fused_kernel(
        const float4* __restrict__ x4,
        const int*    __restrict__ dur_words,
        float4*       __restrict__ out4,
        int mode, float* __restrict__ tail_f, long long* __restrict__ tail_i) {
    int b        = blockIdx.x / BPR;
    int blkInRow = blockIdx.x % BPR;
    int tid  = threadIdx.x;
    int lane = tid & 31;
    int warp = tid >> 5;

    __shared__ int s_is64;
    __shared__ int cum[TT];
    __shared__ int s_wsum[8];
    __shared__ int s_woff[8];

    // --- dtype detection (max word index (31*32+31)*2+1 = 2111: in-bounds
    //     for both the 16384-word int32 and 32768-word int64 buffers; an
    //     int64-LE buffer of values <8 has all odd words zero; int32 random
    //     durations are all-zero with prob 8^-32) ---
    if (warp == 0) {
        int w = dur_words[(b * 32 + lane) * 2 + 1];
        unsigned any = __ballot_sync(0xFFFFFFFFu, w != 0);
        if (lane == 0) s_is64 = (any == 0u) ? 1 : 0;
    }
    __syncthreads();
    int is64 = s_is64;

    // --- load 2 durations per thread, pair-wise inclusive scan ---
    int t0 = tid * 2, t1 = tid * 2 + 1;
    long base = (long)b * TT;
    int d0 = dur_words[is64 ? (base + t0) * 2 : (base + t0)];
    int d1 = dur_words[is64 ? (base + t1) * 2 : (base + t1)];
    int e0 = d0 < 1 ? 1 : d0;
    int e1 = d1 < 1 ? 1 : d1;

    int v = e0 + e1;                       // pair sum
#pragma unroll
    for (int off = 1; off < 32; off <<= 1) {
        int u = __shfl_up_sync(0xFFFFFFFFu, v, off);
        if (lane >= off) v += u;
    }
    if (lane == 31) s_wsum[warp] = v;
    __syncthreads();
    if (warp == 0 && lane < 8) {
        int s = s_wsum[lane];
#pragma unroll
        for (int off = 1; off < 8; off <<= 1) {
            int u = __shfl_up_sync(0xFFu, s, off);
            if (lane >= off) s += u;
        }
        s_woff[lane] = s;
    }
    __syncthreads();
    int inc = v + (warp > 0 ? s_woff[warp - 1] : 0);  // inclusive through t1
    cum[t1] = inc;
    cum[t0] = inc - e1;
    __syncthreads();
    int mel = s_woff[7];                   // row total (== cum[511])

    // --- binary search: lanes 0..3 of each warp search one frame each ---
    int fbase = blkInRow * 32 + warp * 4;  // first of this warp's 4 frames
    int f = fbase + (lane & 3);
    int pos = 0;                           // count of cum[] entries <= f
#pragma unroll
    for (int step = 256; step >= 1; step >>= 1) {
        if (pos + step <= TT && cum[pos + step - 1] <= f) pos += step;
    }
    if (pos > TT - 1) pos = TT - 1;
    int src = (f < mel) ? (int)((b * TT + pos) * D4) : -1;

    int s0 = __shfl_sync(0xFFFFFFFFu, src, 0);
    int s1 = __shfl_sync(0xFFFFFFFFu, src, 1);
    int s2 = __shfl_sync(0xFFFFFFFFu, src, 2);
    int s3 = __shfl_sync(0xFFFFFFFFu, src, 3);

    // --- gather: 3 warp-wide float4 accesses per frame, all independent ---
    const float4 z = make_float4(0.f, 0.f, 0.f, 0.f);
    float4 vv[4][3];
#pragma unroll
    for (int k = 0; k < 3; k++) {
        int o = k * 32 + lane;
        vv[0][k] = (s0 < 0) ? z : __ldg(&x4[s0 + o]);
        vv[1][k] = (s1 < 0) ? z : __ldg(&x4[s1 + o]);
        vv[2][k] = (s2 < 0) ? z : __ldg(&x4[s2 + o]);
        vv[3][k] = (s3 < 0) ? z : __ldg(&x4[s3 + o]);
    }

    float4* obase = out4 + ((long)b * LL + fbase) * D4;
#pragma unroll
    for (int j = 0; j < 4; j++) {
#pragma unroll
        for (int k = 0; k < 3; k++) {
            __stcs(&obase[j * D4 + k * 32 + lane], vv[j][k]);  // streaming store
        }
    }

    // --- mel_len tail (one writer per batch row) ---
    if (blkInRow == 0 && tid == 0) {
        if (mode == 1)      tail_f[b] = (float)mel;
        else if (mode == 2) tail_i[b] = (long long)mel;
    }
}

// ---------------------------------------------------------------------------
extern "C" void kernel_launch(void* const* d_in, const int* in_sizes, int n_in,
                              void* d_out, int out_size) {
    const float* x   = (const float*)d_in[0];
    const int*   dur = (const int*)d_in[1];
    (void)in_sizes; (void)n_in;

    int extra = out_size - MAIN_ELEMS;
    int mode = 0;
    if (extra >= 2 * BB)  mode = 2;   // tail as int64
    else if (extra >= BB) mode = 1;   // tail as fp32

    float*     tail_f = (float*)d_out + MAIN_ELEMS;
    long long* tail_i = (long long*)((char*)d_out + (size_t)MAIN_ELEMS * 4);

    lenreg_fused_kernel<<<NBLK, NTHR>>>((const float4*)x, dur, (float4*)d_out,
                                        mode, tail_f, tail_i);
}